// round 10
// baseline (speedup 1.0000x reference)
#include <cuda_runtime.h>
#include <cstdint>

#define B_SZ 512
#define I_SZ 256
#define H_SZ 512
#define ICH  16

// Transformed parameter planes (recurrent + sensory) and scratch
__device__ float g_SG[H_SZ*H_SZ];
__device__ float g_MS[H_SZ*H_SZ];
__device__ float g_WE[H_SZ*H_SZ];
__device__ float g_WW[H_SZ*H_SZ];
__device__ float s_SG[I_SZ*H_SZ];
__device__ float s_MS[I_SZ*H_SZ];
__device__ float s_WE[I_SZ*H_SZ];
__device__ float s_WW[I_SZ*H_SZ];
__device__ float g_CN[H_SZ];
__device__ float g_CD[H_SZ];
__device__ float g_A [B_SZ*H_SZ];
__device__ float g_Dc[B_SZ*H_SZ];
__device__ float g_v0[B_SZ*H_SZ];
__device__ float g_v1[B_SZ*H_SZ];

// Dynamic SMEM layout (floats):
//   SP: [hf][buf][plane][ICH][64]  -> 2*2*4*ICH*64 = 16384 floats (64KB)
//   VS: [hf][buf][16][20]          -> 2*2*16*20    =  2560 floats (10KB)
#define SP_FLOATS (2*2*4*ICH*64)
#define VS_ROWSTR 20
#define VS_FLOATS (2*2*16*VS_ROWSTR)
#define SMEM_BYTES ((SP_FLOATS + VS_FLOATS) * 4)

__device__ __forceinline__ int SPIX(int hf, int buf, int pl, int ic, int col){
    return (((hf*2 + buf)*4 + pl)*ICH + ic)*64 + col;
}
__device__ __forceinline__ int VSIX(int hf, int buf, int row, int i){
    return SP_FLOATS + ((hf*2 + buf)*16 + row)*VS_ROWSTR + i;
}

__device__ __forceinline__ float tanh_fast(float x){
    float y;
    asm("tanh.approx.f32 %0, %1;" : "=f"(y) : "f"(x));
    return y;
}
__device__ __forceinline__ uint32_t saddr(const void* p){
    return (uint32_t)__cvta_generic_to_shared(p);
}
__device__ __forceinline__ void cp16(uint32_t dst, const void* src){
    asm volatile("cp.async.ca.shared.global [%0], [%1], 16;" :: "r"(dst), "l"(src));
}
__device__ __forceinline__ void bar_half(int hf){
    asm volatile("bar.sync %0, 128;" :: "r"(1 + hf) : "memory");
}

// sigmoid((v-mu)*sigma) = 0.5*tanh(0.5*sigma*v - 0.5*sigma*mu) + 0.5
__global__ void k_prep(const float* __restrict__ mu, const float* __restrict__ sigma,
                       const float* __restrict__ W,  const float* __restrict__ erev,
                       const float* __restrict__ smu, const float* __restrict__ ssig,
                       const float* __restrict__ sW,  const float* __restrict__ serev){
    int idx = blockIdx.x*blockDim.x + threadIdx.x;
    if (idx < H_SZ*H_SZ){
        float s = sigma[idx], m = mu[idx], w = W[idx], e = erev[idx];
        g_SG[idx] = 0.5f*s;
        g_MS[idx] = -0.5f*s*m;
        g_WE[idx] = 0.5f*w*e;
        g_WW[idx] = 0.5f*w;
    } else if (idx < (H_SZ + I_SZ)*H_SZ){
        int j = idx - H_SZ*H_SZ;
        float s = ssig[j], m = smu[j], w = sW[j], e = serev[j];
        s_SG[j] = 0.5f*s;
        s_MS[j] = -0.5f*s*m;
        s_WE[j] = 0.5f*w*e;
        s_WW[j] = 0.5f*w;
    }
}

// Per-h constants: column sums of WE/WW over recurrent (H) + sensory (I) rows
__global__ void k_colsum(){
    int h0 = blockIdx.x * 32;
    int hh = threadIdx.x & 31;
    int it = threadIdx.x >> 5;
    float sn = 0.f, sd = 0.f;
    for (int i = it; i < H_SZ; i += 8){
        sn += g_WE[i*H_SZ + h0 + hh];
        sd += g_WW[i*H_SZ + h0 + hh];
    }
    for (int i = it; i < I_SZ; i += 8){
        sn += s_WE[i*H_SZ + h0 + hh];
        sd += s_WW[i*H_SZ + h0 + hh];
    }
    __shared__ float rn[8][32], rd[8][32];
    rn[it][hh] = sn; rd[it][hh] = sd;
    __syncthreads();
    if (it == 0){
        float a = 0.f, b = 0.f;
        #pragma unroll
        for (int k = 0; k < 8; k++){ a += rn[k][hh]; b += rd[k][hh]; }
        g_CN[h0+hh] = a; g_CD[h0+hh] = b;
    }
}

// ---------------------------------------------------------------------------
// Main loop core, i-split within block. Tile 64h x 16b, 256 threads
// = 2 halves x 4 warps. Lane covers h = h0+2*lane+{0,1} (conflict-free
// LDS.64 params); warp-in-half covers 4 batches (broadcast v).
// Staging via cp.async double buffer (no prefetch regs); per-half named
// barriers in the loop; one __syncthreads only at the final combine.
// Result valid for hf==0 threads (tx < 128).
// ---------------------------------------------------------------------------
template<int HALF_I, int VSTR>
__device__ __forceinline__ void mainloop_core(
        const float* __restrict__ P0, const float* __restrict__ P1,
        const float* __restrict__ P2, const float* __restrict__ P3,
        const float* __restrict__ vin, int h0, int b0, int tx,
        float (&num)[4][2], float (&den)[4][2], float* sm)
{
    const int hf   = tx >> 7;          // half: 0/1
    const int txh  = tx & 127;
    const int lane = tx & 31;
    const int wq   = txh >> 5;         // warp in half: b = b0 + 4*wq + j
    const int ibase = hf * HALF_I;
    const int NC   = HALF_I / ICH;

    auto issue = [&](int c, int buf){
        int i0 = ibase + c * ICH;
        #pragma unroll
        for (int k = 0; k < 8; k++){
            const int pl  = k >> 1;
            const float* base = (pl == 0) ? P0 : (pl == 1) ? P1 : (pl == 2) ? P2 : P3;
            int rem = txh + (k & 1) * 128;     // 0..255
            int row = rem >> 4;                // 0..15
            int col = (rem & 15) * 4;          // 0..60
            cp16(saddr(&sm[SPIX(hf, buf, pl, row, col)]),
                 base + (i0 + row)*H_SZ + h0 + col);
        }
        if (txh < 64){
            int row = txh >> 2;                // 0..15 (batch)
            int col = (txh & 3) * 4;           // 0,4,8,12 (i)
            cp16(saddr(&sm[VSIX(hf, buf, row, col)]),
                 &vin[(b0 + row)*VSTR + i0 + col]);
        }
        asm volatile("cp.async.commit_group;");
    };

    int buf = 0;
    issue(0, 0);
    asm volatile("cp.async.wait_group 0;");
    bar_half(hf);

    for (int c = 0; c < NC; c++){
        if (c + 1 < NC) issue(c + 1, buf ^ 1);
        #pragma unroll 8
        for (int ic = 0; ic < ICH; ic++){
            float2 SG = *(const float2*)&sm[SPIX(hf, buf, 0, ic, 2*lane)];
            float2 MS = *(const float2*)&sm[SPIX(hf, buf, 1, ic, 2*lane)];
            float2 WE = *(const float2*)&sm[SPIX(hf, buf, 2, ic, 2*lane)];
            float2 WW = *(const float2*)&sm[SPIX(hf, buf, 3, ic, 2*lane)];
            #pragma unroll
            for (int j = 0; j < 4; j++){
                float v = sm[VSIX(hf, buf, 4*wq + j, ic)];
                float t0 = tanh_fast(fmaf(v, SG.x, MS.x));
                float t1 = tanh_fast(fmaf(v, SG.y, MS.y));
                num[j][0] = fmaf(WE.x, t0, num[j][0]);
                den[j][0] = fmaf(WW.x, t0, den[j][0]);
                num[j][1] = fmaf(WE.y, t1, num[j][1]);
                den[j][1] = fmaf(WW.y, t1, den[j][1]);
            }
        }
        if (c + 1 < NC){
            asm volatile("cp.async.wait_group 0;");
            bar_half(hf);
            buf ^= 1;
        }
    }

    // Combine halves: half 1 stores partials, half 0 adds them.
    __syncthreads();
    float* red = sm;                   // reuse SP region (needs 2048 floats)
    if (hf == 1){
        #pragma unroll
        for (int j = 0; j < 4; j++){
            #pragma unroll
            for (int k = 0; k < 2; k++){
                red[txh*16 + j*2 + k]     = num[j][k];
                red[txh*16 + j*2 + k + 8] = den[j][k];
            }
        }
    }
    __syncthreads();
    if (hf == 0){
        #pragma unroll
        for (int j = 0; j < 4; j++){
            #pragma unroll
            for (int k = 0; k < 2; k++){
                num[j][k] += red[txh*16 + j*2 + k];
                den[j][k] += red[txh*16 + j*2 + k + 8];
            }
        }
    }
}

// ---------------------------------------------------------------------------
// Sensory pass: writes A[b,h], Dc[b,h] with all constants folded in.
// ---------------------------------------------------------------------------
__global__ __launch_bounds__(256) void k_sensory(
        const float* __restrict__ inp,
        const float* __restrict__ vleak, const float* __restrict__ gleak,
        const float* __restrict__ cm){
    extern __shared__ __align__(16) float sm[];

    const int h0 = blockIdx.x * 64;
    const int b0 = blockIdx.y * 16;
    const int tx = threadIdx.x;

    float num[4][2] = {}, den[4][2] = {};
    mainloop_core<I_SZ/2, I_SZ>(s_SG, s_MS, s_WE, s_WW, inp, h0, b0, tx,
                                num, den, sm);

    if (tx < 128){
        const int lane = tx & 31;
        const int wq   = tx >> 5;
        #pragma unroll
        for (int k = 0; k < 2; k++){
            int h = h0 + 2*lane + k;
            float base_n = fmaf(gleak[h], vleak[h], g_CN[h]);
            float base_d = cm[h] + gleak[h] + g_CD[h];
            #pragma unroll
            for (int j = 0; j < 4; j++){
                int b = b0 + 4*wq + j;
                g_A [b*H_SZ + h] = num[j][k] + base_n;
                g_Dc[b*H_SZ + h] = den[j][k] + base_d;
            }
        }
    }
}

// ---------------------------------------------------------------------------
// One recurrent unfold.
// ---------------------------------------------------------------------------
__global__ __launch_bounds__(256) void k_step(const float* vext, float* voutext,
                                              int sel_in, int sel_out,
                                              const float* __restrict__ cm){
    const float* vin  = (sel_in  == 0) ? g_v0 : ((sel_in  == 1) ? g_v1 : vext);
    float*       vout = (sel_out == 0) ? g_v0 : ((sel_out == 1) ? g_v1 : voutext);

    extern __shared__ __align__(16) float sm[];

    const int h0 = blockIdx.x * 64;
    const int b0 = blockIdx.y * 16;
    const int tx = threadIdx.x;

    float num[4][2] = {}, den[4][2] = {};
    mainloop_core<H_SZ/2, H_SZ>(g_SG, g_MS, g_WE, g_WW, vin, h0, b0, tx,
                                num, den, sm);

    if (tx < 128){
        const int lane = tx & 31;
        const int wq   = tx >> 5;
        #pragma unroll
        for (int k = 0; k < 2; k++){
            int h = h0 + 2*lane + k;
            float cmh = cm[h];
            #pragma unroll
            for (int j = 0; j < 4; j++){
                int b = b0 + 4*wq + j;
                float n = fmaf(cmh, vin[b*H_SZ + h], g_A[b*H_SZ + h]) + num[j][k];
                float d = g_Dc[b*H_SZ + h] + den[j][k];
                vout[b*H_SZ + h] = __fdividef(n, d + 1e-8f);
            }
        }
    }
}

extern "C" void kernel_launch(void* const* d_in, const int* in_sizes, int n_in,
                              void* d_out, int out_size){
    const float* inputs = (const float*)d_in[0];
    const float* state  = (const float*)d_in[1];
    const float* smu    = (const float*)d_in[2];
    const float* ssig   = (const float*)d_in[3];
    const float* sW     = (const float*)d_in[4];
    const float* serev  = (const float*)d_in[5];
    const float* mu     = (const float*)d_in[6];
    const float* sigma  = (const float*)d_in[7];
    const float* W      = (const float*)d_in[8];
    const float* erev   = (const float*)d_in[9];
    const float* vleak  = (const float*)d_in[10];
    const float* gleak  = (const float*)d_in[11];
    const float* cm     = (const float*)d_in[12];
    float* out = (float*)d_out;

    static int attr_done = 0;
    if (!attr_done){
        cudaFuncSetAttribute(k_sensory, cudaFuncAttributeMaxDynamicSharedMemorySize, SMEM_BYTES);
        cudaFuncSetAttribute(k_step,    cudaFuncAttributeMaxDynamicSharedMemorySize, SMEM_BYTES);
        attr_done = 1;
    }

    k_prep<<<((H_SZ+I_SZ)*H_SZ + 255)/256, 256>>>(mu, sigma, W, erev,
                                                  smu, ssig, sW, serev);
    k_colsum<<<H_SZ/32, 256>>>();

    dim3 grid(H_SZ/64, B_SZ/16);   // (8, 32) = 256 blocks, 256 threads each
    k_sensory<<<grid, 256, SMEM_BYTES>>>(inputs, vleak, gleak, cm);

    // 6 unfolds: state -> v0 -> v1 -> v0 -> v1 -> v0 -> out
    k_step<<<grid, 256, SMEM_BYTES>>>(state,   nullptr, 2, 0, cm);
    k_step<<<grid, 256, SMEM_BYTES>>>(nullptr, nullptr, 0, 1, cm);
    k_step<<<grid, 256, SMEM_BYTES>>>(nullptr, nullptr, 1, 0, cm);
    k_step<<<grid, 256, SMEM_BYTES>>>(nullptr, nullptr, 0, 1, cm);
    k_step<<<grid, 256, SMEM_BYTES>>>(nullptr, nullptr, 1, 0, cm);
    k_step<<<grid, 256, SMEM_BYTES>>>(nullptr, out,     0, 2, cm);
}

// round 11
// speedup vs baseline: 1.1754x; 1.1754x over previous
#include <cuda_runtime.h>
#include <cstdint>

#define B_SZ 512
#define I_SZ 256
#define H_SZ 512
#define ICH  16
#define NQ   4

// Transformed parameter planes (recurrent + sensory) and scratch
__device__ float g_SG[H_SZ*H_SZ];
__device__ float g_MS[H_SZ*H_SZ];
__device__ float g_WE[H_SZ*H_SZ];
__device__ float g_WW[H_SZ*H_SZ];
__device__ float s_SG[I_SZ*H_SZ];
__device__ float s_MS[I_SZ*H_SZ];
__device__ float s_WE[I_SZ*H_SZ];
__device__ float s_WW[I_SZ*H_SZ];
__device__ float g_CN[H_SZ];
__device__ float g_CD[H_SZ];
__device__ float g_A [B_SZ*H_SZ];
__device__ float g_Dc[B_SZ*H_SZ];
__device__ float g_v0[B_SZ*H_SZ];
__device__ float g_v1[B_SZ*H_SZ];
// Per-quarter partial sums
__device__ float g_Pn[NQ*B_SZ*H_SZ];
__device__ float g_Pd[NQ*B_SZ*H_SZ];

__device__ __forceinline__ float tanh_fast(float x){
    float y;
    asm("tanh.approx.f32 %0, %1;" : "=f"(y) : "f"(x));
    return y;
}
__device__ __forceinline__ uint32_t saddr(const void* p){
    return (uint32_t)__cvta_generic_to_shared(p);
}
__device__ __forceinline__ void cp16(uint32_t dst, const void* src){
    asm volatile("cp.async.ca.shared.global [%0], [%1], 16;" :: "r"(dst), "l"(src));
}

// sigmoid((v-mu)*sigma) = 0.5*tanh(0.5*sigma*v - 0.5*sigma*mu) + 0.5
__global__ void k_prep(const float* __restrict__ mu, const float* __restrict__ sigma,
                       const float* __restrict__ W,  const float* __restrict__ erev,
                       const float* __restrict__ smu, const float* __restrict__ ssig,
                       const float* __restrict__ sW,  const float* __restrict__ serev){
    int idx = blockIdx.x*blockDim.x + threadIdx.x;
    if (idx < H_SZ*H_SZ){
        float s = sigma[idx], m = mu[idx], w = W[idx], e = erev[idx];
        g_SG[idx] = 0.5f*s;
        g_MS[idx] = -0.5f*s*m;
        g_WE[idx] = 0.5f*w*e;
        g_WW[idx] = 0.5f*w;
    } else if (idx < (H_SZ + I_SZ)*H_SZ){
        int j = idx - H_SZ*H_SZ;
        float s = ssig[j], m = smu[j], w = sW[j], e = serev[j];
        s_SG[j] = 0.5f*s;
        s_MS[j] = -0.5f*s*m;
        s_WE[j] = 0.5f*w*e;
        s_WW[j] = 0.5f*w;
    }
}

// Per-h constants: column sums of WE/WW over recurrent (H) + sensory (I) rows
__global__ void k_colsum(){
    int h0 = blockIdx.x * 32;
    int hh = threadIdx.x & 31;
    int it = threadIdx.x >> 5;
    float sn = 0.f, sd = 0.f;
    for (int i = it; i < H_SZ; i += 8){
        sn += g_WE[i*H_SZ + h0 + hh];
        sd += g_WW[i*H_SZ + h0 + hh];
    }
    for (int i = it; i < I_SZ; i += 8){
        sn += s_WE[i*H_SZ + h0 + hh];
        sd += s_WW[i*H_SZ + h0 + hh];
    }
    __shared__ float rn[8][32], rd[8][32];
    rn[it][hh] = sn; rd[it][hh] = sd;
    __syncthreads();
    if (it == 0){
        float a = 0.f, b = 0.f;
        #pragma unroll
        for (int k = 0; k < 8; k++){ a += rn[k][hh]; b += rd[k][hh]; }
        g_CN[h0+hh] = a; g_CD[h0+hh] = b;
    }
}

// ---------------------------------------------------------------------------
// Partial core: one block = 64h x 16b tile x one i-quarter. 128 threads =
// 4 warps; lane covers h = h0+2*lane+{0,1} (conflict-free LDS.64 params);
// warp wq covers b = b0+4*wq+{0..3} (broadcast v). cp.async double buffer.
// ---------------------------------------------------------------------------
template<int QI, int VSTR>
__device__ __forceinline__ void partial_core(
        const float* __restrict__ P0, const float* __restrict__ P1,
        const float* __restrict__ P2, const float* __restrict__ P3,
        const float* __restrict__ vin, int h0, int b0, int ibase, int tx,
        float (&num)[4][2], float (&den)[4][2],
        float (*sp)[4][ICH][64], float (*vs)[16][ICH])
{
    const int lane = tx & 31;
    const int wq   = tx >> 5;
    const int NC   = QI / ICH;

    auto issue = [&](int c, int buf){
        int i0 = ibase + c * ICH;
        #pragma unroll
        for (int k = 0; k < 8; k++){
            const int pl = k >> 1;
            const float* base = (pl == 0) ? P0 : (pl == 1) ? P1 : (pl == 2) ? P2 : P3;
            int rem = tx + (k & 1) * 128;      // 0..255
            int row = rem >> 4;                // 0..15
            int col = (rem & 15) * 4;          // 0..60
            cp16(saddr(&sp[buf][pl][row][col]), base + (i0 + row)*H_SZ + h0 + col);
        }
        if (tx < 64){
            int row = tx >> 2;                 // 0..15 (batch)
            int col = (tx & 3) * 4;            // 0,4,8,12 (i)
            cp16(saddr(&vs[buf][row][col]), &vin[(b0 + row)*VSTR + i0 + col]);
        }
        asm volatile("cp.async.commit_group;");
    };

    int buf = 0;
    issue(0, 0);
    asm volatile("cp.async.wait_group 0;");
    __syncthreads();

    for (int c = 0; c < NC; c++){
        if (c + 1 < NC) issue(c + 1, buf ^ 1);
        #pragma unroll 8
        for (int ic = 0; ic < ICH; ic++){
            float2 SG = *(const float2*)&sp[buf][0][ic][2*lane];
            float2 MS = *(const float2*)&sp[buf][1][ic][2*lane];
            float2 WE = *(const float2*)&sp[buf][2][ic][2*lane];
            float2 WW = *(const float2*)&sp[buf][3][ic][2*lane];
            #pragma unroll
            for (int j = 0; j < 4; j++){
                float v = vs[buf][4*wq + j][ic];
                float t0 = tanh_fast(fmaf(v, SG.x, MS.x));
                float t1 = tanh_fast(fmaf(v, SG.y, MS.y));
                num[j][0] = fmaf(WE.x, t0, num[j][0]);
                den[j][0] = fmaf(WW.x, t0, den[j][0]);
                num[j][1] = fmaf(WE.y, t1, num[j][1]);
                den[j][1] = fmaf(WW.y, t1, den[j][1]);
            }
        }
        if (c + 1 < NC){
            asm volatile("cp.async.wait_group 0;");
            __syncthreads();
            buf ^= 1;
        }
    }
}

__device__ __forceinline__ void store_partials(int h0, int b0, int qt, int tx,
                                               float (&num)[4][2], float (&den)[4][2]){
    const int lane = tx & 31;
    const int wq   = tx >> 5;
    #pragma unroll
    for (int j = 0; j < 4; j++){
        int b = b0 + 4*wq + j;
        int ix = (qt*B_SZ + b)*H_SZ + h0 + 2*lane;
        *(float2*)&g_Pn[ix] = make_float2(num[j][0], num[j][1]);
        *(float2*)&g_Pd[ix] = make_float2(den[j][0], den[j][1]);
    }
}

// Recurrent partial: grid (8, 32, 4)
__global__ __launch_bounds__(128, 6) void k_step_partial(const float* vext, int sel_in){
    const float* vin = (sel_in == 0) ? g_v0 : ((sel_in == 1) ? g_v1 : vext);
    __shared__ __align__(16) float sp[2][4][ICH][64];
    __shared__ __align__(16) float vs[2][16][ICH];
    const int h0 = blockIdx.x * 64, b0 = blockIdx.y * 16, qt = blockIdx.z;
    const int tx = threadIdx.x;
    float num[4][2] = {}, den[4][2] = {};
    partial_core<H_SZ/NQ, H_SZ>(g_SG, g_MS, g_WE, g_WW, vin,
                                h0, b0, qt*(H_SZ/NQ), tx, num, den, sp, vs);
    store_partials(h0, b0, qt, tx, num, den);
}

// Sensory partial: grid (8, 32, 4)
__global__ __launch_bounds__(128, 6) void k_sens_partial(const float* __restrict__ inp){
    __shared__ __align__(16) float sp[2][4][ICH][64];
    __shared__ __align__(16) float vs[2][16][ICH];
    const int h0 = blockIdx.x * 64, b0 = blockIdx.y * 16, qt = blockIdx.z;
    const int tx = threadIdx.x;
    float num[4][2] = {}, den[4][2] = {};
    partial_core<I_SZ/NQ, I_SZ>(s_SG, s_MS, s_WE, s_WW, inp,
                                h0, b0, qt*(I_SZ/NQ), tx, num, den, sp, vs);
    store_partials(h0, b0, qt, tx, num, den);
}

// Sensory combine: A/Dc = per-h constants + sum of quarter partials.
__global__ __launch_bounds__(256) void k_sens_combine(
        const float* __restrict__ vleak, const float* __restrict__ gleak,
        const float* __restrict__ cm){
    int e = (blockIdx.x*256 + threadIdx.x) * 4;
    int h = e & (H_SZ - 1);
    float4 gl = *(const float4*)&gleak[h];
    float4 vl = *(const float4*)&vleak[h];
    float4 c4 = *(const float4*)&cm[h];
    float4 cn = *(const float4*)&g_CN[h];
    float4 cd = *(const float4*)&g_CD[h];
    float4 n, d;
    n.x = fmaf(gl.x, vl.x, cn.x); n.y = fmaf(gl.y, vl.y, cn.y);
    n.z = fmaf(gl.z, vl.z, cn.z); n.w = fmaf(gl.w, vl.w, cn.w);
    d.x = c4.x + gl.x + cd.x; d.y = c4.y + gl.y + cd.y;
    d.z = c4.z + gl.z + cd.z; d.w = c4.w + gl.w + cd.w;
    #pragma unroll
    for (int q = 0; q < NQ; q++){
        float4 pn = *(const float4*)&g_Pn[q*B_SZ*H_SZ + e];
        float4 pd = *(const float4*)&g_Pd[q*B_SZ*H_SZ + e];
        n.x += pn.x; n.y += pn.y; n.z += pn.z; n.w += pn.w;
        d.x += pd.x; d.y += pd.y; d.z += pd.z; d.w += pd.w;
    }
    *(float4*)&g_A[e]  = n;
    *(float4*)&g_Dc[e] = d;
}

// Step combine: vout = (cm*vin + A + sum Pn) / (Dc + sum Pd + 1e-8)
__global__ __launch_bounds__(256) void k_step_combine(
        const float* vext, float* voutext, int sel_in, int sel_out,
        const float* __restrict__ cm){
    const float* vin  = (sel_in  == 0) ? g_v0 : ((sel_in  == 1) ? g_v1 : vext);
    float*       vout = (sel_out == 0) ? g_v0 : ((sel_out == 1) ? g_v1 : voutext);
    int e = (blockIdx.x*256 + threadIdx.x) * 4;
    int h = e & (H_SZ - 1);
    float4 v4 = *(const float4*)&vin[e];
    float4 a4 = *(const float4*)&g_A[e];
    float4 d4 = *(const float4*)&g_Dc[e];
    float4 c4 = *(const float4*)&cm[h];
    float4 n;
    n.x = fmaf(c4.x, v4.x, a4.x); n.y = fmaf(c4.y, v4.y, a4.y);
    n.z = fmaf(c4.z, v4.z, a4.z); n.w = fmaf(c4.w, v4.w, a4.w);
    #pragma unroll
    for (int q = 0; q < NQ; q++){
        float4 pn = *(const float4*)&g_Pn[q*B_SZ*H_SZ + e];
        float4 pd = *(const float4*)&g_Pd[q*B_SZ*H_SZ + e];
        n.x += pn.x; n.y += pn.y; n.z += pn.z; n.w += pn.w;
        d4.x += pd.x; d4.y += pd.y; d4.z += pd.z; d4.w += pd.w;
    }
    float4 o;
    o.x = __fdividef(n.x, d4.x + 1e-8f);
    o.y = __fdividef(n.y, d4.y + 1e-8f);
    o.z = __fdividef(n.z, d4.z + 1e-8f);
    o.w = __fdividef(n.w, d4.w + 1e-8f);
    *(float4*)&vout[e] = o;
}

extern "C" void kernel_launch(void* const* d_in, const int* in_sizes, int n_in,
                              void* d_out, int out_size){
    const float* inputs = (const float*)d_in[0];
    const float* state  = (const float*)d_in[1];
    const float* smu    = (const float*)d_in[2];
    const float* ssig   = (const float*)d_in[3];
    const float* sW     = (const float*)d_in[4];
    const float* serev  = (const float*)d_in[5];
    const float* mu     = (const float*)d_in[6];
    const float* sigma  = (const float*)d_in[7];
    const float* W      = (const float*)d_in[8];
    const float* erev   = (const float*)d_in[9];
    const float* vleak  = (const float*)d_in[10];
    const float* gleak  = (const float*)d_in[11];
    const float* cm     = (const float*)d_in[12];
    float* out = (float*)d_out;

    k_prep<<<((H_SZ+I_SZ)*H_SZ + 255)/256, 256>>>(mu, sigma, W, erev,
                                                  smu, ssig, sW, serev);
    k_colsum<<<H_SZ/32, 256>>>();

    dim3 pgrid(H_SZ/64, B_SZ/16, NQ);       // (8, 32, 4) = 1024 blocks
    const int cgrid = B_SZ*H_SZ/(256*4);    // 256 blocks

    k_sens_partial<<<pgrid, 128>>>(inputs);
    k_sens_combine<<<cgrid, 256>>>(vleak, gleak, cm);

    // 6 unfolds: state -> v0 -> v1 -> v0 -> v1 -> v0 -> out
    const int seq_in [6] = {2, 0, 1, 0, 1, 0};
    const int seq_out[6] = {0, 1, 0, 1, 0, 2};
    for (int s = 0; s < 6; s++){
        const float* vext = (seq_in[s]  == 2) ? state : nullptr;
        float*       oext = (seq_out[s] == 2) ? out   : nullptr;
        k_step_partial<<<pgrid, 128>>>(vext, seq_in[s]);
        k_step_combine<<<cgrid, 256>>>(vext, oext, seq_in[s], seq_out[s], cm);
    }
}

// round 12
// speedup vs baseline: 1.1770x; 1.0014x over previous
#include <cuda_runtime.h>
#include <cstdint>

#define B_SZ 512
#define I_SZ 256
#define H_SZ 512
#define ICH  16
#define NQ   4

// Transformed parameter planes (recurrent + sensory) and scratch
__device__ float g_SG[H_SZ*H_SZ];
__device__ float g_MS[H_SZ*H_SZ];
__device__ float g_WE[H_SZ*H_SZ];
__device__ float g_WW[H_SZ*H_SZ];
__device__ float s_SG[I_SZ*H_SZ];
__device__ float s_MS[I_SZ*H_SZ];
__device__ float s_WE[I_SZ*H_SZ];
__device__ float s_WW[I_SZ*H_SZ];
__device__ float g_CN[H_SZ];
__device__ float g_CD[H_SZ];
__device__ float g_A [B_SZ*H_SZ];
__device__ float g_Dc[B_SZ*H_SZ];
__device__ float g_v0[B_SZ*H_SZ];
__device__ float g_v1[B_SZ*H_SZ];
// Per-quarter partial sums (recurrent steps) and sensory partials
__device__ float g_Pn[NQ*B_SZ*H_SZ];
__device__ float g_Pd[NQ*B_SZ*H_SZ];
__device__ float g_PnS[NQ*B_SZ*H_SZ];
__device__ float g_PdS[NQ*B_SZ*H_SZ];

__device__ __forceinline__ float tanh_fast(float x){
    float y;
    asm("tanh.approx.f32 %0, %1;" : "=f"(y) : "f"(x));
    return y;
}
__device__ __forceinline__ uint32_t saddr(const void* p){
    return (uint32_t)__cvta_generic_to_shared(p);
}
__device__ __forceinline__ void cp16(uint32_t dst, const void* src){
    asm volatile("cp.async.ca.shared.global [%0], [%1], 16;" :: "r"(dst), "l"(src));
}

// sigmoid((v-mu)*sigma) = 0.5*tanh(0.5*sigma*v - 0.5*sigma*mu) + 0.5
__global__ void k_prep(const float* __restrict__ mu, const float* __restrict__ sigma,
                       const float* __restrict__ W,  const float* __restrict__ erev,
                       const float* __restrict__ smu, const float* __restrict__ ssig,
                       const float* __restrict__ sW,  const float* __restrict__ serev){
    int idx = blockIdx.x*blockDim.x + threadIdx.x;
    if (idx < H_SZ*H_SZ){
        float s = sigma[idx], m = mu[idx], w = W[idx], e = erev[idx];
        g_SG[idx] = 0.5f*s;
        g_MS[idx] = -0.5f*s*m;
        g_WE[idx] = 0.5f*w*e;
        g_WW[idx] = 0.5f*w;
    } else if (idx < (H_SZ + I_SZ)*H_SZ){
        int j = idx - H_SZ*H_SZ;
        float s = ssig[j], m = smu[j], w = sW[j], e = serev[j];
        s_SG[j] = 0.5f*s;
        s_MS[j] = -0.5f*s*m;
        s_WE[j] = 0.5f*w*e;
        s_WW[j] = 0.5f*w;
    }
}

// Per-h constants: column sums of WE/WW over recurrent (H) + sensory (I) rows
__global__ void k_colsum(){
    int h0 = blockIdx.x * 32;
    int hh = threadIdx.x & 31;
    int it = threadIdx.x >> 5;
    float sn = 0.f, sd = 0.f;
    for (int i = it; i < H_SZ; i += 8){
        sn += g_WE[i*H_SZ + h0 + hh];
        sd += g_WW[i*H_SZ + h0 + hh];
    }
    for (int i = it; i < I_SZ; i += 8){
        sn += s_WE[i*H_SZ + h0 + hh];
        sd += s_WW[i*H_SZ + h0 + hh];
    }
    __shared__ float rn[8][32], rd[8][32];
    rn[it][hh] = sn; rd[it][hh] = sd;
    __syncthreads();
    if (it == 0){
        float a = 0.f, b = 0.f;
        #pragma unroll
        for (int k = 0; k < 8; k++){ a += rn[k][hh]; b += rd[k][hh]; }
        g_CN[h0+hh] = a; g_CD[h0+hh] = b;
    }
}

// ---------------------------------------------------------------------------
// Partial core: one block = 64h x 16b tile x one i-quarter. 128 threads =
// 4 warps; lane covers h = h0+2*lane+{0,1} (conflict-free LDS.64 params);
// warp wq covers b = b0+4*wq+{0..3} (broadcast v). cp.async double buffer.
// ---------------------------------------------------------------------------
template<int QI, int VSTR>
__device__ __forceinline__ void partial_core(
        const float* __restrict__ P0, const float* __restrict__ P1,
        const float* __restrict__ P2, const float* __restrict__ P3,
        const float* __restrict__ vin, int h0, int b0, int ibase, int tx,
        float (&num)[4][2], float (&den)[4][2],
        float (*sp)[4][ICH][64], float (*vs)[16][ICH])
{
    const int lane = tx & 31;
    const int wq   = tx >> 5;
    const int NC   = QI / ICH;

    auto issue = [&](int c, int buf){
        int i0 = ibase + c * ICH;
        #pragma unroll
        for (int k = 0; k < 8; k++){
            const int pl = k >> 1;
            const float* base = (pl == 0) ? P0 : (pl == 1) ? P1 : (pl == 2) ? P2 : P3;
            int rem = tx + (k & 1) * 128;      // 0..255
            int row = rem >> 4;                // 0..15
            int col = (rem & 15) * 4;          // 0..60
            cp16(saddr(&sp[buf][pl][row][col]), base + (i0 + row)*H_SZ + h0 + col);
        }
        if (tx < 64){
            int row = tx >> 2;                 // 0..15 (batch)
            int col = (tx & 3) * 4;            // 0,4,8,12 (i)
            cp16(saddr(&vs[buf][row][col]), &vin[(b0 + row)*VSTR + i0 + col]);
        }
        asm volatile("cp.async.commit_group;");
    };

    int buf = 0;
    issue(0, 0);
    asm volatile("cp.async.wait_group 0;");
    __syncthreads();

    for (int c = 0; c < NC; c++){
        if (c + 1 < NC) issue(c + 1, buf ^ 1);
        #pragma unroll 8
        for (int ic = 0; ic < ICH; ic++){
            float2 SG = *(const float2*)&sp[buf][0][ic][2*lane];
            float2 MS = *(const float2*)&sp[buf][1][ic][2*lane];
            float2 WE = *(const float2*)&sp[buf][2][ic][2*lane];
            float2 WW = *(const float2*)&sp[buf][3][ic][2*lane];
            #pragma unroll
            for (int j = 0; j < 4; j++){
                float v = vs[buf][4*wq + j][ic];
                float t0 = tanh_fast(fmaf(v, SG.x, MS.x));
                float t1 = tanh_fast(fmaf(v, SG.y, MS.y));
                num[j][0] = fmaf(WE.x, t0, num[j][0]);
                den[j][0] = fmaf(WW.x, t0, den[j][0]);
                num[j][1] = fmaf(WE.y, t1, num[j][1]);
                den[j][1] = fmaf(WW.y, t1, den[j][1]);
            }
        }
        if (c + 1 < NC){
            asm volatile("cp.async.wait_group 0;");
            __syncthreads();
            buf ^= 1;
        }
    }
}

__device__ __forceinline__ void store_partials(float* Pn, float* Pd,
                                               int h0, int b0, int qt, int tx,
                                               float (&num)[4][2], float (&den)[4][2]){
    const int lane = tx & 31;
    const int wq   = tx >> 5;
    #pragma unroll
    for (int j = 0; j < 4; j++){
        int b = b0 + 4*wq + j;
        int ix = (qt*B_SZ + b)*H_SZ + h0 + 2*lane;
        *(float2*)&Pn[ix] = make_float2(num[j][0], num[j][1]);
        *(float2*)&Pd[ix] = make_float2(den[j][0], den[j][1]);
    }
}

// Recurrent partial: grid (8, 32, 4)
__global__ __launch_bounds__(128, 6) void k_step_partial(const float* vext, int sel_in){
    const float* vin = (sel_in == 0) ? g_v0 : ((sel_in == 1) ? g_v1 : vext);
    __shared__ __align__(16) float sp[2][4][ICH][64];
    __shared__ __align__(16) float vs[2][16][ICH];
    const int h0 = blockIdx.x * 64, b0 = blockIdx.y * 16, qt = blockIdx.z;
    const int tx = threadIdx.x;
    float num[4][2] = {}, den[4][2] = {};
    partial_core<H_SZ/NQ, H_SZ>(g_SG, g_MS, g_WE, g_WW, vin,
                                h0, b0, qt*(H_SZ/NQ), tx, num, den, sp, vs);
    store_partials(g_Pn, g_Pd, h0, b0, qt, tx, num, den);
}

// Sensory partial: grid (8, 32, 4) — separate scratch so it can overlap step 1
__global__ __launch_bounds__(128, 6) void k_sens_partial(const float* __restrict__ inp){
    __shared__ __align__(16) float sp[2][4][ICH][64];
    __shared__ __align__(16) float vs[2][16][ICH];
    const int h0 = blockIdx.x * 64, b0 = blockIdx.y * 16, qt = blockIdx.z;
    const int tx = threadIdx.x;
    float num[4][2] = {}, den[4][2] = {};
    partial_core<I_SZ/NQ, I_SZ>(s_SG, s_MS, s_WE, s_WW, inp,
                                h0, b0, qt*(I_SZ/NQ), tx, num, den, sp, vs);
    store_partials(g_PnS, g_PdS, h0, b0, qt, tx, num, den);
}

// Step combine. first=1: also build A/Dc from sensory partials + constants.
// vout = (cm*vin + A + sum Pn) / (Dc + sum Pd + 1e-8)
__global__ __launch_bounds__(128) void k_step_combine(
        const float* vext, float* voutext, int sel_in, int sel_out, int first,
        const float* __restrict__ cm, const float* __restrict__ gleak,
        const float* __restrict__ vleak){
    const float* vin  = (sel_in  == 0) ? g_v0 : ((sel_in  == 1) ? g_v1 : vext);
    float*       vout = (sel_out == 0) ? g_v0 : ((sel_out == 1) ? g_v1 : voutext);
    int e = (blockIdx.x*128 + threadIdx.x) * 4;
    int h = e & (H_SZ - 1);

    float4 a4, d4;
    if (first){
        float4 gl = *(const float4*)&gleak[h];
        float4 vl = *(const float4*)&vleak[h];
        float4 c4 = *(const float4*)&cm[h];
        float4 cn = *(const float4*)&g_CN[h];
        float4 cd = *(const float4*)&g_CD[h];
        a4.x = fmaf(gl.x, vl.x, cn.x); a4.y = fmaf(gl.y, vl.y, cn.y);
        a4.z = fmaf(gl.z, vl.z, cn.z); a4.w = fmaf(gl.w, vl.w, cn.w);
        d4.x = c4.x + gl.x + cd.x; d4.y = c4.y + gl.y + cd.y;
        d4.z = c4.z + gl.z + cd.z; d4.w = c4.w + gl.w + cd.w;
        #pragma unroll
        for (int q = 0; q < NQ; q++){
            float4 pn = *(const float4*)&g_PnS[q*B_SZ*H_SZ + e];
            float4 pd = *(const float4*)&g_PdS[q*B_SZ*H_SZ + e];
            a4.x += pn.x; a4.y += pn.y; a4.z += pn.z; a4.w += pn.w;
            d4.x += pd.x; d4.y += pd.y; d4.z += pd.z; d4.w += pd.w;
        }
        *(float4*)&g_A[e]  = a4;
        *(float4*)&g_Dc[e] = d4;
    } else {
        a4 = *(const float4*)&g_A[e];
        d4 = *(const float4*)&g_Dc[e];
    }

    float4 v4 = *(const float4*)&vin[e];
    float4 c4 = *(const float4*)&cm[h];
    float4 n;
    n.x = fmaf(c4.x, v4.x, a4.x); n.y = fmaf(c4.y, v4.y, a4.y);
    n.z = fmaf(c4.z, v4.z, a4.z); n.w = fmaf(c4.w, v4.w, a4.w);
    #pragma unroll
    for (int q = 0; q < NQ; q++){
        float4 pn = *(const float4*)&g_Pn[q*B_SZ*H_SZ + e];
        float4 pd = *(const float4*)&g_Pd[q*B_SZ*H_SZ + e];
        n.x += pn.x; n.y += pn.y; n.z += pn.z; n.w += pn.w;
        d4.x += pd.x; d4.y += pd.y; d4.z += pd.z; d4.w += pd.w;
    }
    float4 o;
    o.x = __fdividef(n.x, d4.x + 1e-8f);
    o.y = __fdividef(n.y, d4.y + 1e-8f);
    o.z = __fdividef(n.z, d4.z + 1e-8f);
    o.w = __fdividef(n.w, d4.w + 1e-8f);
    *(float4*)&vout[e] = o;
}

extern "C" void kernel_launch(void* const* d_in, const int* in_sizes, int n_in,
                              void* d_out, int out_size){
    const float* inputs = (const float*)d_in[0];
    const float* state  = (const float*)d_in[1];
    const float* smu    = (const float*)d_in[2];
    const float* ssig   = (const float*)d_in[3];
    const float* sW     = (const float*)d_in[4];
    const float* serev  = (const float*)d_in[5];
    const float* mu     = (const float*)d_in[6];
    const float* sigma  = (const float*)d_in[7];
    const float* W      = (const float*)d_in[8];
    const float* erev   = (const float*)d_in[9];
    const float* vleak  = (const float*)d_in[10];
    const float* gleak  = (const float*)d_in[11];
    const float* cm     = (const float*)d_in[12];
    float* out = (float*)d_out;

    k_prep<<<((H_SZ+I_SZ)*H_SZ + 255)/256, 256>>>(mu, sigma, W, erev,
                                                  smu, ssig, sW, serev);
    k_colsum<<<H_SZ/32, 256>>>();

    dim3 pgrid(H_SZ/64, B_SZ/16, NQ);           // (8, 32, 4) = 1024 blocks
    const int cgrid = B_SZ*H_SZ/(128*4);        // 512 blocks x 128 threads

    // Sensory partials (separate scratch) then straight into step 1 partials —
    // no combine in between; step-1 combine builds A/Dc inline.
    k_sens_partial<<<pgrid, 128>>>(inputs);

    // 6 unfolds: state -> v0 -> v1 -> v0 -> v1 -> v0 -> out
    const int seq_in [6] = {2, 0, 1, 0, 1, 0};
    const int seq_out[6] = {0, 1, 0, 1, 0, 2};
    for (int s = 0; s < 6; s++){
        const float* vext = (seq_in[s]  == 2) ? state : nullptr;
        float*       oext = (seq_out[s] == 2) ? out   : nullptr;
        k_step_partial<<<pgrid, 128>>>(vext, seq_in[s]);
        k_step_combine<<<cgrid, 128>>>(vext, oext, seq_in[s], seq_out[s],
                                       s == 0 ? 1 : 0, cm, gleak, vleak);
    }
}

// round 13
// speedup vs baseline: 1.2396x; 1.0531x over previous
#include <cuda_runtime.h>
#include <cstdint>

#define B_SZ 512
#define I_SZ 256
#define H_SZ 512
#define ICH  8
#define NQ   4
#define NQS  2

// Transformed parameter planes (recurrent + sensory) and scratch
__device__ float g_SG[H_SZ*H_SZ];
__device__ float g_MS[H_SZ*H_SZ];
__device__ float g_WE[H_SZ*H_SZ];
__device__ float g_WW[H_SZ*H_SZ];
__device__ float s_SG[I_SZ*H_SZ];
__device__ float s_MS[I_SZ*H_SZ];
__device__ float s_WE[I_SZ*H_SZ];
__device__ float s_WW[I_SZ*H_SZ];
__device__ float g_CN[H_SZ];
__device__ float g_CD[H_SZ];
__device__ float g_A [B_SZ*H_SZ];
__device__ float g_Dc[B_SZ*H_SZ];
__device__ float g_v0[B_SZ*H_SZ];
__device__ float g_v1[B_SZ*H_SZ];
// Per-quarter partial sums (recurrent steps) and sensory partials (halves)
__device__ float g_Pn[NQ*B_SZ*H_SZ];
__device__ float g_Pd[NQ*B_SZ*H_SZ];
__device__ float g_PnS[NQS*B_SZ*H_SZ];
__device__ float g_PdS[NQS*B_SZ*H_SZ];

__device__ __forceinline__ float tanh_fast(float x){
    float y;
    asm("tanh.approx.f32 %0, %1;" : "=f"(y) : "f"(x));
    return y;
}
__device__ __forceinline__ uint32_t saddr(const void* p){
    return (uint32_t)__cvta_generic_to_shared(p);
}
__device__ __forceinline__ void cp16(uint32_t dst, const void* src){
    asm volatile("cp.async.ca.shared.global [%0], [%1], 16;" :: "r"(dst), "l"(src));
}

// sigmoid((v-mu)*sigma) = 0.5*tanh(0.5*sigma*v - 0.5*sigma*mu) + 0.5
__global__ void k_prep(const float* __restrict__ mu, const float* __restrict__ sigma,
                       const float* __restrict__ W,  const float* __restrict__ erev,
                       const float* __restrict__ smu, const float* __restrict__ ssig,
                       const float* __restrict__ sW,  const float* __restrict__ serev){
    int idx = blockIdx.x*blockDim.x + threadIdx.x;
    if (idx < H_SZ*H_SZ){
        float s = sigma[idx], m = mu[idx], w = W[idx], e = erev[idx];
        g_SG[idx] = 0.5f*s;
        g_MS[idx] = -0.5f*s*m;
        g_WE[idx] = 0.5f*w*e;
        g_WW[idx] = 0.5f*w;
    } else if (idx < (H_SZ + I_SZ)*H_SZ){
        int j = idx - H_SZ*H_SZ;
        float s = ssig[j], m = smu[j], w = sW[j], e = serev[j];
        s_SG[j] = 0.5f*s;
        s_MS[j] = -0.5f*s*m;
        s_WE[j] = 0.5f*w*e;
        s_WW[j] = 0.5f*w;
    }
}

// Per-h constants from RAW inputs (independent of k_prep):
// CN[h] = 0.5*( sum_i W*erev (recur) + sum_i sW*serev (sens) ), CD likewise with W.
__global__ void k_colsum(const float* __restrict__ W,  const float* __restrict__ erev,
                         const float* __restrict__ sW, const float* __restrict__ serev){
    int h0 = blockIdx.x * 32;
    int hh = threadIdx.x & 31;
    int it = threadIdx.x >> 5;
    float sn = 0.f, sd = 0.f;
    for (int i = it; i < H_SZ; i += 8){
        float w = W[i*H_SZ + h0 + hh], e = erev[i*H_SZ + h0 + hh];
        sn = fmaf(w, e, sn); sd += w;
    }
    for (int i = it; i < I_SZ; i += 8){
        float w = sW[i*H_SZ + h0 + hh], e = serev[i*H_SZ + h0 + hh];
        sn = fmaf(w, e, sn); sd += w;
    }
    __shared__ float rn[8][32], rd[8][32];
    rn[it][hh] = sn; rd[it][hh] = sd;
    __syncthreads();
    if (it == 0){
        float a = 0.f, b = 0.f;
        #pragma unroll
        for (int k = 0; k < 8; k++){ a += rn[k][hh]; b += rd[k][hh]; }
        g_CN[h0+hh] = 0.5f*a; g_CD[h0+hh] = 0.5f*b;
    }
}

// ---------------------------------------------------------------------------
// Partial core: one block = 64h x 16b tile x 128 i-rows. 128 threads = 4 warps;
// lane covers h = h0+2*lane+{0,1} (conflict-free LDS.64 params); warp wq covers
// b = b0+4*wq+{0..3} (broadcast v). cp.async double buffer. QI = 128.
// ---------------------------------------------------------------------------
__device__ __forceinline__ void partial_core(
        const float* __restrict__ P0, const float* __restrict__ P1,
        const float* __restrict__ P2, const float* __restrict__ P3,
        const float* __restrict__ vin, int vstr, int h0, int b0, int ibase, int tx,
        float (&num)[4][2], float (&den)[4][2],
        float (*sp)[4][ICH][64], float (*vs)[16][ICH])
{
    const int lane = tx & 31;
    const int wq   = tx >> 5;
    const int NC   = 128 / ICH;        // 16 chunks

    // params: per plane 8 ic x 64 h = 512 floats = 128 cp16 -> 1 per thread
    const int prow = tx >> 4;          // 0..7
    const int pcol = (tx & 15) * 4;    // 0..60
    // v: 16 b x 8 i = 128 floats = 32 cp16 (tx < 32)
    const int vrow = tx >> 1;          // 0..15 (batch)
    const int vcol = (tx & 1) * 4;     // 0 or 4 (i)

    auto issue = [&](int c, int buf){
        int i0 = ibase + c * ICH;
        const float* bases[4] = {P0, P1, P2, P3};
        #pragma unroll
        for (int pl = 0; pl < 4; pl++)
            cp16(saddr(&sp[buf][pl][prow][pcol]), bases[pl] + (i0 + prow)*H_SZ + h0 + pcol);
        if (tx < 32)
            cp16(saddr(&vs[buf][vrow][vcol]), &vin[(b0 + vrow)*vstr + i0 + vcol]);
        asm volatile("cp.async.commit_group;");
    };

    int buf = 0;
    issue(0, 0);
    asm volatile("cp.async.wait_group 0;");
    __syncthreads();

    for (int c = 0; c < NC; c++){
        if (c + 1 < NC) issue(c + 1, buf ^ 1);
        #pragma unroll
        for (int ic = 0; ic < ICH; ic++){
            float2 SG = *(const float2*)&sp[buf][0][ic][2*lane];
            float2 MS = *(const float2*)&sp[buf][1][ic][2*lane];
            float2 WE = *(const float2*)&sp[buf][2][ic][2*lane];
            float2 WW = *(const float2*)&sp[buf][3][ic][2*lane];
            #pragma unroll
            for (int j = 0; j < 4; j++){
                float v = vs[buf][4*wq + j][ic];
                float t0 = tanh_fast(fmaf(v, SG.x, MS.x));
                float t1 = tanh_fast(fmaf(v, SG.y, MS.y));
                num[j][0] = fmaf(WE.x, t0, num[j][0]);
                den[j][0] = fmaf(WW.x, t0, den[j][0]);
                num[j][1] = fmaf(WE.y, t1, num[j][1]);
                den[j][1] = fmaf(WW.y, t1, den[j][1]);
            }
        }
        if (c + 1 < NC){
            asm volatile("cp.async.wait_group 0;");
            __syncthreads();
            buf ^= 1;
        }
    }
}

__device__ __forceinline__ void store_partials(float* Pn, float* Pd,
                                               int h0, int b0, int qt, int tx,
                                               float (&num)[4][2], float (&den)[4][2]){
    const int lane = tx & 31;
    const int wq   = tx >> 5;
    #pragma unroll
    for (int j = 0; j < 4; j++){
        int b = b0 + 4*wq + j;
        int ix = (qt*B_SZ + b)*H_SZ + h0 + 2*lane;
        *(float2*)&Pn[ix] = make_float2(num[j][0], num[j][1]);
        *(float2*)&Pd[ix] = make_float2(den[j][0], den[j][1]);
    }
}

// Recurrent partial; when with_sens, grid.z = 6 and z in [4,6) computes the
// sensory halves (inputs, I-planes) into g_PnS/g_PdS.
__global__ __launch_bounds__(128, 8) void k_step_partial(
        const float* vext, int sel_in, const float* __restrict__ inp, int with_sens){
    __shared__ __align__(16) float sp[2][4][ICH][64];
    __shared__ __align__(16) float vs[2][16][ICH];
    const int h0 = blockIdx.x * 64, b0 = blockIdx.y * 16, qt = blockIdx.z;
    const int tx = threadIdx.x;
    float num[4][2] = {}, den[4][2] = {};

    if (with_sens && qt >= NQ){
        int qs = qt - NQ;                       // sensory half 0/1
        partial_core(s_SG, s_MS, s_WE, s_WW, inp, I_SZ,
                     h0, b0, qs*128, tx, num, den, sp, vs);
        store_partials(g_PnS, g_PdS, h0, b0, qs, tx, num, den);
    } else {
        const float* vin = (sel_in == 0) ? g_v0 : ((sel_in == 1) ? g_v1 : vext);
        partial_core(g_SG, g_MS, g_WE, g_WW, vin, H_SZ,
                     h0, b0, qt*128, tx, num, den, sp, vs);
        store_partials(g_Pn, g_Pd, h0, b0, qt, tx, num, den);
    }
}

// Step combine. first=1: also build A/Dc from sensory partials + constants.
// vout = (cm*vin + A + sum Pn) / (Dc + sum Pd + 1e-8)
__global__ __launch_bounds__(128) void k_step_combine(
        const float* vext, float* voutext, int sel_in, int sel_out, int first,
        const float* __restrict__ cm, const float* __restrict__ gleak,
        const float* __restrict__ vleak){
    const float* vin  = (sel_in  == 0) ? g_v0 : ((sel_in  == 1) ? g_v1 : vext);
    float*       vout = (sel_out == 0) ? g_v0 : ((sel_out == 1) ? g_v1 : voutext);
    int e = (blockIdx.x*128 + threadIdx.x) * 4;
    int h = e & (H_SZ - 1);

    float4 a4, d4;
    if (first){
        float4 gl = *(const float4*)&gleak[h];
        float4 vl = *(const float4*)&vleak[h];
        float4 c4 = *(const float4*)&cm[h];
        float4 cn = *(const float4*)&g_CN[h];
        float4 cd = *(const float4*)&g_CD[h];
        a4.x = fmaf(gl.x, vl.x, cn.x); a4.y = fmaf(gl.y, vl.y, cn.y);
        a4.z = fmaf(gl.z, vl.z, cn.z); a4.w = fmaf(gl.w, vl.w, cn.w);
        d4.x = c4.x + gl.x + cd.x; d4.y = c4.y + gl.y + cd.y;
        d4.z = c4.z + gl.z + cd.z; d4.w = c4.w + gl.w + cd.w;
        #pragma unroll
        for (int q = 0; q < NQS; q++){
            float4 pn = *(const float4*)&g_PnS[q*B_SZ*H_SZ + e];
            float4 pd = *(const float4*)&g_PdS[q*B_SZ*H_SZ + e];
            a4.x += pn.x; a4.y += pn.y; a4.z += pn.z; a4.w += pn.w;
            d4.x += pd.x; d4.y += pd.y; d4.z += pd.z; d4.w += pd.w;
        }
        *(float4*)&g_A[e]  = a4;
        *(float4*)&g_Dc[e] = d4;
    } else {
        a4 = *(const float4*)&g_A[e];
        d4 = *(const float4*)&g_Dc[e];
    }

    float4 v4 = *(const float4*)&vin[e];
    float4 c4 = *(const float4*)&cm[h];
    float4 n;
    n.x = fmaf(c4.x, v4.x, a4.x); n.y = fmaf(c4.y, v4.y, a4.y);
    n.z = fmaf(c4.z, v4.z, a4.z); n.w = fmaf(c4.w, v4.w, a4.w);
    #pragma unroll
    for (int q = 0; q < NQ; q++){
        float4 pn = *(const float4*)&g_Pn[q*B_SZ*H_SZ + e];
        float4 pd = *(const float4*)&g_Pd[q*B_SZ*H_SZ + e];
        n.x += pn.x; n.y += pn.y; n.z += pn.z; n.w += pn.w;
        d4.x += pd.x; d4.y += pd.y; d4.z += pd.z; d4.w += pd.w;
    }
    float4 o;
    o.x = __fdividef(n.x, d4.x + 1e-8f);
    o.y = __fdividef(n.y, d4.y + 1e-8f);
    o.z = __fdividef(n.z, d4.z + 1e-8f);
    o.w = __fdividef(n.w, d4.w + 1e-8f);
    *(float4*)&vout[e] = o;
}

extern "C" void kernel_launch(void* const* d_in, const int* in_sizes, int n_in,
                              void* d_out, int out_size){
    const float* inputs = (const float*)d_in[0];
    const float* state  = (const float*)d_in[1];
    const float* smu    = (const float*)d_in[2];
    const float* ssig   = (const float*)d_in[3];
    const float* sW     = (const float*)d_in[4];
    const float* serev  = (const float*)d_in[5];
    const float* mu     = (const float*)d_in[6];
    const float* sigma  = (const float*)d_in[7];
    const float* W      = (const float*)d_in[8];
    const float* erev   = (const float*)d_in[9];
    const float* vleak  = (const float*)d_in[10];
    const float* gleak  = (const float*)d_in[11];
    const float* cm     = (const float*)d_in[12];
    float* out = (float*)d_out;

    k_prep<<<((H_SZ+I_SZ)*H_SZ + 255)/256, 256>>>(mu, sigma, W, erev,
                                                  smu, ssig, sW, serev);
    k_colsum<<<H_SZ/32, 256>>>(W, erev, sW, serev);

    dim3 pgrid6(H_SZ/64, B_SZ/16, NQ + NQS);    // (8, 32, 6): step1 + sensory
    dim3 pgrid4(H_SZ/64, B_SZ/16, NQ);          // (8, 32, 4)
    const int cgrid = B_SZ*H_SZ/(128*4);        // 512 blocks x 128 threads

    // 6 unfolds: state -> v0 -> v1 -> v0 -> v1 -> v0 -> out
    const int seq_in [6] = {2, 0, 1, 0, 1, 0};
    const int seq_out[6] = {0, 1, 0, 1, 0, 2};
    for (int s = 0; s < 6; s++){
        const float* vext = (seq_in[s]  == 2) ? state : nullptr;
        float*       oext = (seq_out[s] == 2) ? out   : nullptr;
        if (s == 0)
            k_step_partial<<<pgrid6, 128>>>(vext, seq_in[s], inputs, 1);
        else
            k_step_partial<<<pgrid4, 128>>>(vext, seq_in[s], nullptr, 0);
        k_step_combine<<<cgrid, 128>>>(vext, oext, seq_in[s], seq_out[s],
                                       s == 0 ? 1 : 0, cm, gleak, vleak);
    }
}

// round 14
// speedup vs baseline: 1.2495x; 1.0080x over previous
#include <cuda_runtime.h>
#include <cstdint>

#define B_SZ 512
#define I_SZ 256
#define H_SZ 512
#define ICH  8
#define NQ   4
#define NQS  2

// Transformed parameter planes (recurrent + sensory) and scratch
__device__ float g_SG[H_SZ*H_SZ];
__device__ float g_MS[H_SZ*H_SZ];
__device__ float g_WE[H_SZ*H_SZ];
__device__ float g_WW[H_SZ*H_SZ];
__device__ float s_SG[I_SZ*H_SZ];
__device__ float s_MS[I_SZ*H_SZ];
__device__ float s_WE[I_SZ*H_SZ];
__device__ float s_WW[I_SZ*H_SZ];
__device__ float g_CN[H_SZ];
__device__ float g_CD[H_SZ];
__device__ float g_A [B_SZ*H_SZ];
__device__ float g_Dc[B_SZ*H_SZ];
__device__ float g_v0[B_SZ*H_SZ];
__device__ float g_v1[B_SZ*H_SZ];
// Per-quarter partial sums (recurrent steps) and sensory partials (halves)
__device__ float g_Pn[NQ*B_SZ*H_SZ];
__device__ float g_Pd[NQ*B_SZ*H_SZ];
__device__ float g_PnS[NQS*B_SZ*H_SZ];
__device__ float g_PdS[NQS*B_SZ*H_SZ];

__device__ __forceinline__ float tanh_fast(float x){
    float y;
    asm("tanh.approx.f32 %0, %1;" : "=f"(y) : "f"(x));
    return y;
}
__device__ __forceinline__ uint32_t saddr(const void* p){
    return (uint32_t)__cvta_generic_to_shared(p);
}
__device__ __forceinline__ void cp16(uint32_t dst, const void* src){
    asm volatile("cp.async.ca.shared.global [%0], [%1], 16;" :: "r"(dst), "l"(src));
}

// sigmoid((v-mu)*sigma) = 0.5*tanh(0.5*sigma*v - 0.5*sigma*mu) + 0.5
__global__ void k_prep(const float* __restrict__ mu, const float* __restrict__ sigma,
                       const float* __restrict__ W,  const float* __restrict__ erev,
                       const float* __restrict__ smu, const float* __restrict__ ssig,
                       const float* __restrict__ sW,  const float* __restrict__ serev){
    int idx = blockIdx.x*blockDim.x + threadIdx.x;
    if (idx < H_SZ*H_SZ){
        float s = sigma[idx], m = mu[idx], w = W[idx], e = erev[idx];
        g_SG[idx] = 0.5f*s;
        g_MS[idx] = -0.5f*s*m;
        g_WE[idx] = 0.5f*w*e;
        g_WW[idx] = 0.5f*w;
    } else if (idx < (H_SZ + I_SZ)*H_SZ){
        int j = idx - H_SZ*H_SZ;
        float s = ssig[j], m = smu[j], w = sW[j], e = serev[j];
        s_SG[j] = 0.5f*s;
        s_MS[j] = -0.5f*s*m;
        s_WE[j] = 0.5f*w*e;
        s_WW[j] = 0.5f*w;
    }
}

// Per-h constants from RAW inputs:
// CN[h] = 0.5*( sum_i W*erev (recur) + sum_i sW*serev (sens) ), CD likewise.
__global__ void k_colsum(const float* __restrict__ W,  const float* __restrict__ erev,
                         const float* __restrict__ sW, const float* __restrict__ serev){
    int h0 = blockIdx.x * 32;
    int hh = threadIdx.x & 31;
    int it = threadIdx.x >> 5;
    float sn = 0.f, sd = 0.f;
    for (int i = it; i < H_SZ; i += 8){
        float w = W[i*H_SZ + h0 + hh], e = erev[i*H_SZ + h0 + hh];
        sn = fmaf(w, e, sn); sd += w;
    }
    for (int i = it; i < I_SZ; i += 8){
        float w = sW[i*H_SZ + h0 + hh], e = serev[i*H_SZ + h0 + hh];
        sn = fmaf(w, e, sn); sd += w;
    }
    __shared__ float rn[8][32], rd[8][32];
    rn[it][hh] = sn; rd[it][hh] = sd;
    __syncthreads();
    if (it == 0){
        float a = 0.f, b = 0.f;
        #pragma unroll
        for (int k = 0; k < 8; k++){ a += rn[k][hh]; b += rd[k][hh]; }
        g_CN[h0+hh] = 0.5f*a; g_CD[h0+hh] = 0.5f*b;
    }
}

// ---------------------------------------------------------------------------
// Partial core: one block = 64h x 16b tile x 128 i-rows. 128 threads = 4 warps;
// lane covers h = h0+2*lane+{0,1} (conflict-free LDS.64 params); warp wq covers
// b = b0+4*wq+{0..3} (broadcast v). cp.async double buffer. QI = 128.
// ---------------------------------------------------------------------------
__device__ __forceinline__ void partial_core(
        const float* __restrict__ P0, const float* __restrict__ P1,
        const float* __restrict__ P2, const float* __restrict__ P3,
        const float* __restrict__ vin, int vstr, int h0, int b0, int ibase, int tx,
        float (&num)[4][2], float (&den)[4][2],
        float (*sp)[4][ICH][64], float (*vs)[16][ICH])
{
    const int lane = tx & 31;
    const int wq   = tx >> 5;
    const int NC   = 128 / ICH;        // 16 chunks

    const int prow = tx >> 4;          // 0..7
    const int pcol = (tx & 15) * 4;    // 0..60
    const int vrow = tx >> 1;          // 0..15 (batch)
    const int vcol = (tx & 1) * 4;     // 0 or 4 (i)

    auto issue = [&](int c, int buf){
        int i0 = ibase + c * ICH;
        const float* bases[4] = {P0, P1, P2, P3};
        #pragma unroll
        for (int pl = 0; pl < 4; pl++)
            cp16(saddr(&sp[buf][pl][prow][pcol]), bases[pl] + (i0 + prow)*H_SZ + h0 + pcol);
        if (tx < 32)
            cp16(saddr(&vs[buf][vrow][vcol]), &vin[(b0 + vrow)*vstr + i0 + vcol]);
        asm volatile("cp.async.commit_group;");
    };

    int buf = 0;
    issue(0, 0);
    asm volatile("cp.async.wait_group 0;");
    __syncthreads();

    for (int c = 0; c < NC; c++){
        if (c + 1 < NC) issue(c + 1, buf ^ 1);
        #pragma unroll
        for (int ic = 0; ic < ICH; ic++){
            float2 SG = *(const float2*)&sp[buf][0][ic][2*lane];
            float2 MS = *(const float2*)&sp[buf][1][ic][2*lane];
            float2 WE = *(const float2*)&sp[buf][2][ic][2*lane];
            float2 WW = *(const float2*)&sp[buf][3][ic][2*lane];
            #pragma unroll
            for (int j = 0; j < 4; j++){
                float v = vs[buf][4*wq + j][ic];
                float t0 = tanh_fast(fmaf(v, SG.x, MS.x));
                float t1 = tanh_fast(fmaf(v, SG.y, MS.y));
                num[j][0] = fmaf(WE.x, t0, num[j][0]);
                den[j][0] = fmaf(WW.x, t0, den[j][0]);
                num[j][1] = fmaf(WE.y, t1, num[j][1]);
                den[j][1] = fmaf(WW.y, t1, den[j][1]);
            }
        }
        if (c + 1 < NC){
            asm volatile("cp.async.wait_group 0;");
            __syncthreads();
            buf ^= 1;
        }
    }
}

__device__ __forceinline__ void store_partials(float* Pn, float* Pd,
                                               int h0, int b0, int qt, int tx,
                                               float (&num)[4][2], float (&den)[4][2]){
    const int lane = tx & 31;
    const int wq   = tx >> 5;
    #pragma unroll
    for (int j = 0; j < 4; j++){
        int b = b0 + 4*wq + j;
        int ix = (qt*B_SZ + b)*H_SZ + h0 + 2*lane;
        *(float2*)&Pn[ix] = make_float2(num[j][0], num[j][1]);
        *(float2*)&Pd[ix] = make_float2(den[j][0], den[j][1]);
    }
}

// Recurrent partial; when with_sens, grid.z = 6 and z in [4,6) computes the
// sensory halves (inputs, I-planes) into g_PnS/g_PdS.
__global__ __launch_bounds__(128, 8) void k_step_partial(
        const float* vext, int sel_in, const float* __restrict__ inp, int with_sens){
    __shared__ __align__(16) float sp[2][4][ICH][64];
    __shared__ __align__(16) float vs[2][16][ICH];
    const int h0 = blockIdx.x * 64, b0 = blockIdx.y * 16, qt = blockIdx.z;
    const int tx = threadIdx.x;
    float num[4][2] = {}, den[4][2] = {};

    if (with_sens && qt >= NQ){
        int qs = qt - NQ;                       // sensory half 0/1
        partial_core(s_SG, s_MS, s_WE, s_WW, inp, I_SZ,
                     h0, b0, qs*128, tx, num, den, sp, vs);
        store_partials(g_PnS, g_PdS, h0, b0, qs, tx, num, den);
    } else {
        const float* vin = (sel_in == 0) ? g_v0 : ((sel_in == 1) ? g_v1 : vext);
        partial_core(g_SG, g_MS, g_WE, g_WW, vin, H_SZ,
                     h0, b0, qt*128, tx, num, den, sp, vs);
        store_partials(g_Pn, g_Pd, h0, b0, qt, tx, num, den);
    }
}

// Step combine: 512 blocks x 256 threads, float2 per thread (2x warps of the
// old float4 shape -> double the latency coverage on the partial reads).
// first=1: also build A/Dc from sensory partials + constants.
__global__ __launch_bounds__(256) void k_step_combine(
        const float* vext, float* voutext, int sel_in, int sel_out, int first,
        const float* __restrict__ cm, const float* __restrict__ gleak,
        const float* __restrict__ vleak){
    const float* vin  = (sel_in  == 0) ? g_v0 : ((sel_in  == 1) ? g_v1 : vext);
    float*       vout = (sel_out == 0) ? g_v0 : ((sel_out == 1) ? g_v1 : voutext);
    int e = (blockIdx.x*256 + threadIdx.x) * 2;
    int h = e & (H_SZ - 1);

    float2 a2, d2;
    if (first){
        float2 gl = *(const float2*)&gleak[h];
        float2 vl = *(const float2*)&vleak[h];
        float2 c2 = *(const float2*)&cm[h];
        float2 cn = *(const float2*)&g_CN[h];
        float2 cd = *(const float2*)&g_CD[h];
        a2.x = fmaf(gl.x, vl.x, cn.x); a2.y = fmaf(gl.y, vl.y, cn.y);
        d2.x = c2.x + gl.x + cd.x;     d2.y = c2.y + gl.y + cd.y;
        #pragma unroll
        for (int q = 0; q < NQS; q++){
            float2 pn = __ldg((const float2*)&g_PnS[q*B_SZ*H_SZ + e]);
            float2 pd = __ldg((const float2*)&g_PdS[q*B_SZ*H_SZ + e]);
            a2.x += pn.x; a2.y += pn.y;
            d2.x += pd.x; d2.y += pd.y;
        }
        *(float2*)&g_A[e]  = a2;
        *(float2*)&g_Dc[e] = d2;
    } else {
        a2 = *(const float2*)&g_A[e];
        d2 = *(const float2*)&g_Dc[e];
    }

    float2 v2 = *(const float2*)&vin[e];
    float2 c2 = *(const float2*)&cm[h];
    float2 n;
    n.x = fmaf(c2.x, v2.x, a2.x); n.y = fmaf(c2.y, v2.y, a2.y);
    #pragma unroll
    for (int q = 0; q < NQ; q++){
        float2 pn = __ldg((const float2*)&g_Pn[q*B_SZ*H_SZ + e]);
        float2 pd = __ldg((const float2*)&g_Pd[q*B_SZ*H_SZ + e]);
        n.x += pn.x; n.y += pn.y;
        d2.x += pd.x; d2.y += pd.y;
    }
    float2 o;
    o.x = __fdividef(n.x, d2.x + 1e-8f);
    o.y = __fdividef(n.y, d2.y + 1e-8f);
    *(float2*)&vout[e] = o;
}

extern "C" void kernel_launch(void* const* d_in, const int* in_sizes, int n_in,
                              void* d_out, int out_size){
    const float* inputs = (const float*)d_in[0];
    const float* state  = (const float*)d_in[1];
    const float* smu    = (const float*)d_in[2];
    const float* ssig   = (const float*)d_in[3];
    const float* sW     = (const float*)d_in[4];
    const float* serev  = (const float*)d_in[5];
    const float* mu     = (const float*)d_in[6];
    const float* sigma  = (const float*)d_in[7];
    const float* W      = (const float*)d_in[8];
    const float* erev   = (const float*)d_in[9];
    const float* vleak  = (const float*)d_in[10];
    const float* gleak  = (const float*)d_in[11];
    const float* cm     = (const float*)d_in[12];
    float* out = (float*)d_out;

    k_prep<<<((H_SZ+I_SZ)*H_SZ + 255)/256, 256>>>(mu, sigma, W, erev,
                                                  smu, ssig, sW, serev);
    k_colsum<<<H_SZ/32, 256>>>(W, erev, sW, serev);

    dim3 pgrid6(H_SZ/64, B_SZ/16, NQ + NQS);    // (8, 32, 6): step1 + sensory
    dim3 pgrid4(H_SZ/64, B_SZ/16, NQ);          // (8, 32, 4)
    const int cgrid = B_SZ*H_SZ/(256*2);        // 512 blocks x 256 threads

    // 6 unfolds: state -> v0 -> v1 -> v0 -> v1 -> v0 -> out
    const int seq_in [6] = {2, 0, 1, 0, 1, 0};
    const int seq_out[6] = {0, 1, 0, 1, 0, 2};
    for (int s = 0; s < 6; s++){
        const float* vext = (seq_in[s]  == 2) ? state : nullptr;
        float*       oext = (seq_out[s] == 2) ? out   : nullptr;
        if (s == 0)
            k_step_partial<<<pgrid6, 128>>>(vext, seq_in[s], inputs, 1);
        else
            k_step_partial<<<pgrid4, 128>>>(vext, seq_in[s], nullptr, 0);
        k_step_combine<<<cgrid, 256>>>(vext, oext, seq_in[s], seq_out[s],
                                       s == 0 ? 1 : 0, cm, gleak, vleak);
    }
}